// round 9
// baseline (speedup 1.0000x reference)
#include <cuda_runtime.h>
#include <cuda_fp16.h>
#include <math.h>

// Problem capacities (fixed by the dataset: N=100000, E=1600000)
#define NMAX 100096
#define EMAX 1600000

// -------- scratch (alloc-free: __device__ globals) --------
__device__ float   g_ps[NMAX];          // per-node edge-score scalar
__device__ __half2 g_vh[NMAX * 32];     // node values tanh(xWv^T+bv), fp16, 64 cols
__device__ float   g_h1[NMAX * 64];     // layer-1 output (fp32, feeds layer-2 GEMM)
__device__ float   g_ex[EMAX];          // exp(edge logit) — fallback path only
__device__ int     g_rowptr[NMAX + 1];
__device__ int     g_cnt[NMAX];
__device__ int     g_dstc[EMAX];

// -------------------- CSR build --------------------
__global__ void k_count(const int* __restrict__ src, int E) {
    int e = blockIdx.x * blockDim.x + threadIdx.x;
    if (e < E) atomicAdd(&g_cnt[src[e]], 1);
}

__global__ void k_scan(int N, int E) {
    __shared__ int sh[1024];
    int t = threadIdx.x;
    int chunk = (N + 1023) / 1024;
    int start = t * chunk;
    int end = min(start + chunk, N);
    int s = 0;
    for (int i = start; i < end; i++) s += g_cnt[i];
    sh[t] = s;
    __syncthreads();
    for (int off = 1; off < 1024; off <<= 1) {
        int v = 0;
        if (t >= off) v = sh[t - off];
        __syncthreads();
        if (t >= off) sh[t] += v;
        __syncthreads();
    }
    int run = (t == 0) ? 0 : sh[t - 1];
    for (int i = start; i < end; i++) {
        int c = g_cnt[i];
        g_rowptr[i] = run;
        g_cnt[i] = 0;
        run += c;
    }
    if (t == 1023) g_rowptr[N] = sh[1023];
}

__global__ void k_scatter(const int* __restrict__ src, const int* __restrict__ dst, int E) {
    int e = blockIdx.x * blockDim.x + threadIdx.x;
    if (e < E) {
        int s = src[e];
        int p = g_rowptr[s] + atomicAdd(&g_cnt[s], 1);
        g_dstc[p] = dst[e];
    }
}

// -------------------- fused GEMM: full-W smem + double-buffered X --------------------
// vh[N,32] (half2) = tanh(X[N,K] @ Wv^T + bv)
// ps[N]            = tanh(X[N,K] @ Wa^T + ba) · We
// dynamic smem: Was[K][64] | Wvs[K][64] | Xs[2][16][128]
#define BM 128
#define BK 16

__global__ __launch_bounds__(256, 2) void k_gemm2(
    const float* __restrict__ X, int N, int K,
    const float* __restrict__ Wa, const float* __restrict__ ba,
    const float* __restrict__ We,
    const float* __restrict__ Wv, const float* __restrict__ bv,
    float* __restrict__ ps, __half2* __restrict__ vh)
{
    extern __shared__ __align__(16) float smem[];
    float* Was = smem;              // K*64
    float* Wvs = smem + K * 64;     // K*64
    float* Xs  = smem + 2 * K * 64; // 2*16*128

    int tid = threadIdx.x;
    int bm = blockIdx.x * BM;
    int tr = tid >> 4;        // 0..15 : row group (8 rows)
    int tc = tid & 15;        // 0..15 : col group (4 cols)

    // ---- preload full W (transposed to [k][out]) ----
    for (int i = tid; i < K * 16; i += 256) {
        int row = i & 63;          // output index
        int kb = i >> 6;           // float4 index along k
        float4 qa = *(const float4*)&Wa[(size_t)row * K + kb * 4];
        float4 qv = *(const float4*)&Wv[(size_t)row * K + kb * 4];
        Was[(kb * 4 + 0) * 64 + row] = qa.x; Was[(kb * 4 + 1) * 64 + row] = qa.y;
        Was[(kb * 4 + 2) * 64 + row] = qa.z; Was[(kb * 4 + 3) * 64 + row] = qa.w;
        Wvs[(kb * 4 + 0) * 64 + row] = qv.x; Wvs[(kb * 4 + 1) * 64 + row] = qv.y;
        Wvs[(kb * 4 + 2) * 64 + row] = qv.z; Wvs[(kb * 4 + 3) * 64 + row] = qv.w;
    }

    // X tile load helper indices: per thread 2 float4
    int xrow0 = tid >> 2;                 // 0..63
    int xk4   = (tid & 3) * 4;            // 0,4,8,12
    float4 xf[2];

    // prefetch tile 0
    {
        int gm0 = bm + xrow0, gm1 = bm + xrow0 + 64;
        xf[0] = (gm0 < N) ? *(const float4*)&X[(size_t)gm0 * K + xk4] : make_float4(0,0,0,0);
        xf[1] = (gm1 < N) ? *(const float4*)&X[(size_t)gm1 * K + xk4] : make_float4(0,0,0,0);
    }
    // store tile 0 to buffer 0
    #pragma unroll
    for (int j = 0; j < 2; j++) {
        int row = xrow0 + j * 64;
        Xs[(xk4 + 0) * 128 + row] = xf[j].x; Xs[(xk4 + 1) * 128 + row] = xf[j].y;
        Xs[(xk4 + 2) * 128 + row] = xf[j].z; Xs[(xk4 + 3) * 128 + row] = xf[j].w;
    }
    __syncthreads();

    float cV[8][4] = {};
    float cA[8][4] = {};

    int T = K / BK;
    for (int t = 0; t < T; t++) {
        // prefetch next tile into registers
        if (t + 1 < T) {
            int koff = (t + 1) * BK + xk4;
            int gm0 = bm + xrow0, gm1 = bm + xrow0 + 64;
            xf[0] = (gm0 < N) ? *(const float4*)&X[(size_t)gm0 * K + koff] : make_float4(0,0,0,0);
            xf[1] = (gm1 < N) ? *(const float4*)&X[(size_t)gm1 * K + koff] : make_float4(0,0,0,0);
        }
        // compute current tile
        const float* Xb = Xs + (t & 1) * (BK * 128);
        const float* Wab = Was + t * BK * 64;
        const float* Wvb = Wvs + t * BK * 64;
        #pragma unroll
        for (int k = 0; k < BK; k++) {
            float4 x0 = *(const float4*)&Xb[k * 128 + tr * 8];
            float4 x1 = *(const float4*)&Xb[k * 128 + tr * 8 + 4];
            float4 wa4 = *(const float4*)&Wab[k * 64 + tc * 4];
            float4 wv4 = *(const float4*)&Wvb[k * 64 + tc * 4];
            float a0[8] = {x0.x, x0.y, x0.z, x0.w, x1.x, x1.y, x1.z, x1.w};
            float wa[4] = {wa4.x, wa4.y, wa4.z, wa4.w};
            float wv[4] = {wv4.x, wv4.y, wv4.z, wv4.w};
            #pragma unroll
            for (int i = 0; i < 8; i++)
                #pragma unroll
                for (int j = 0; j < 4; j++) {
                    cV[i][j] = fmaf(a0[i], wv[j], cV[i][j]);
                    cA[i][j] = fmaf(a0[i], wa[j], cA[i][j]);
                }
        }
        // store prefetched tile (buffer last read at t-1; synced then)
        if (t + 1 < T) {
            float* Xn = Xs + ((t + 1) & 1) * (BK * 128);
            #pragma unroll
            for (int j = 0; j < 2; j++) {
                int row = xrow0 + j * 64;
                Xn[(xk4 + 0) * 128 + row] = xf[j].x; Xn[(xk4 + 1) * 128 + row] = xf[j].y;
                Xn[(xk4 + 2) * 128 + row] = xf[j].z; Xn[(xk4 + 3) * 128 + row] = xf[j].w;
            }
            __syncthreads();
        }
    }

    float we_r[4], ba_r[4], bv_r[4];
    #pragma unroll
    for (int j = 0; j < 4; j++) {
        int jj = tc * 4 + j;
        we_r[j] = We[jj]; ba_r[j] = ba[jj]; bv_r[j] = bv[jj];
    }

    #pragma unroll
    for (int i = 0; i < 8; i++) {
        float pacc = 0.f;
        float vj[4];
        #pragma unroll
        for (int j = 0; j < 4; j++) {
            vj[j] = tanhf(cV[i][j] + bv_r[j]);
            pacc = fmaf(tanhf(cA[i][j] + ba_r[j]), we_r[j], pacc);
        }
        #pragma unroll
        for (int off = 8; off > 0; off >>= 1)
            pacc += __shfl_xor_sync(0xffffffffu, pacc, off);
        int gm = bm + tr * 8 + i;
        if (gm < N) {
            __half2 hv[2];
            hv[0] = __floats2half2_rn(vj[0], vj[1]);
            hv[1] = __floats2half2_rn(vj[2], vj[3]);
            *(uint2*)&vh[(size_t)gm * 32 + tc * 2] = *(uint2*)hv;
            if (tc == 0) ps[gm] = pacc;
        }
    }
}

// ---------- fused softmax + aggregation + row std-norm (warp per node) ----------
__global__ __launch_bounds__(256) void k_agg(
    const float* __restrict__ ps, const float* __restrict__ be,
    float* __restrict__ Out, int N)
{
    int wid = (blockIdx.x * blockDim.x + threadIdx.x) >> 5;
    int lane = threadIdx.x & 31;
    if (wid >= N) return;

    int r0 = g_rowptr[wid];
    int r1 = g_rowptr[wid + 1];
    int deg = r1 - r0;
    float pr = ps[wid] + be[0];

    int g = lane >> 3;    // 0..3  edge within group-of-4
    int c = lane & 7;     // 0..7  column chunk (8 cols)
    const uint4* v4 = (const uint4*)g_vh;    // v row = 8 uint4 (64 fp16)
    float acc[8] = {};

    if (deg <= 32) {
        // ---- register-resident softmax: one edge per lane ----
        float ex = 0.f;
        int d = 0;
        if (lane < deg) {
            d = g_dstc[r0 + lane];
            ex = expf(tanhf(pr + ps[d]));   // |tanh|<1 -> safe without max-sub
        }
        float sum = ex;
        #pragma unroll
        for (int off = 16; off > 0; off >>= 1) sum += __shfl_xor_sync(0xffffffffu, sum, off);
        float att = ex * (1.0f / sum);      // lanes >= deg hold att = 0

        // 8 edges per iteration: two independent 4-edge batches (MLP=2), no loads for att/d
        for (int i0 = 0; i0 < deg; i0 += 8) {
            int j0 = i0 + g;                 // <= 34 < 32? (i0<deg<=32, g<=3 -> j0<=34) -- but
            int j1 = i0 + 4 + g;             // i0 max = ((deg-1)/8)*8 <= 24, so j1 <= 31
            j0 &= 31; j1 &= 31;              // safety clamp (att of those lanes is 0 anyway)
            float a0 = __shfl_sync(0xffffffffu, att, j0);
            int   d0 = __shfl_sync(0xffffffffu, d,   j0);
            float a1 = __shfl_sync(0xffffffffu, att, j1);
            int   d1 = __shfl_sync(0xffffffffu, d,   j1);
            uint4 q0 = v4[(size_t)d0 * 8 + c];
            uint4 q1 = v4[(size_t)d1 * 8 + c];
            const __half2* h0 = (const __half2*)&q0;
            const __half2* h1 = (const __half2*)&q1;
            #pragma unroll
            for (int t = 0; t < 4; t++) {
                float2 f0 = __half22float2(h0[t]);
                float2 f1 = __half22float2(h1[t]);
                acc[2 * t]     = fmaf(a0, f0.x, acc[2 * t]);
                acc[2 * t + 1] = fmaf(a0, f0.y, acc[2 * t + 1]);
                acc[2 * t]     = fmaf(a1, f1.x, acc[2 * t]);
                acc[2 * t + 1] = fmaf(a1, f1.y, acc[2 * t + 1]);
            }
        }
    } else {
        // ---- fallback (rare: deg > 32): two-pass via g_ex ----
        float sum = 0.f;
        for (int p = r0 + lane; p < r1; p += 32) {
            int d = g_dstc[p];
            float e = expf(tanhf(pr + ps[d]));
            g_ex[p] = e;
            sum += e;
        }
        #pragma unroll
        for (int off = 16; off > 0; off >>= 1) sum += __shfl_xor_sync(0xffffffffu, sum, off);
        float inv = 1.0f / sum;

        for (int base = r0; base < r1; base += 4) {
            int p = base + g;
            float att = 0.f;
            int d = 0;
            if (p < r1) {
                att = g_ex[p] * inv;
                d = g_dstc[p];
            }
            uint4 q = v4[(size_t)d * 8 + c];
            const __half2* hq = (const __half2*)&q;
            #pragma unroll
            for (int t = 0; t < 4; t++) {
                float2 f = __half22float2(hq[t]);
                acc[2 * t]     = fmaf(att, f.x, acc[2 * t]);
                acc[2 * t + 1] = fmaf(att, f.y, acc[2 * t + 1]);
            }
        }
    }

    // reduce across the 4 edge-groups (lane bits 3,4)
    #pragma unroll
    for (int t = 0; t < 8; t++) {
        acc[t] += __shfl_xor_sync(0xffffffffu, acc[t], 8);
        acc[t] += __shfl_xor_sync(0xffffffffu, acc[t], 16);
    }

    // row stats over 64 cols: butterfly across c bits only (g copies identical)
    float s = 0.f;
    #pragma unroll
    for (int t = 0; t < 8; t++) s += acc[t];
    #pragma unroll
    for (int off = 4; off > 0; off >>= 1) s += __shfl_xor_sync(0xffffffffu, s, off);
    float mean = s * (1.0f / 64.0f);
    float q2 = 0.f;
    #pragma unroll
    for (int t = 0; t < 8; t++) { float dq = acc[t] - mean; q2 = fmaf(dq, dq, q2); }
    #pragma unroll
    for (int off = 4; off > 0; off >>= 1) q2 += __shfl_xor_sync(0xffffffffu, q2, off);
    float inv_std = rsqrtf(q2 * (1.0f / 63.0f));

    if (g < 2) {
        float4 o;
        o.x = acc[g * 4 + 0] * inv_std;
        o.y = acc[g * 4 + 1] * inv_std;
        o.z = acc[g * 4 + 2] * inv_std;
        o.w = acc[g * 4 + 3] * inv_std;
        *(float4*)&Out[(size_t)wid * 64 + c * 8 + g * 4] = o;
    }
}

// -------------------- launch --------------------
extern "C" void kernel_launch(void* const* d_in, const int* in_sizes, int n_in,
                              void* d_out, int out_size)
{
    const float* h   = (const float*)d_in[0];
    const int*   ei  = (const int*)d_in[1];
    const float* W11 = (const float*)d_in[2];
    const float* b11 = (const float*)d_in[3];
    const float* W12 = (const float*)d_in[4];
    const float* b12 = (const float*)d_in[5];
    const float* W13 = (const float*)d_in[6];
    const float* b13 = (const float*)d_in[7];
    const float* W21 = (const float*)d_in[8];
    const float* b21 = (const float*)d_in[9];
    const float* W22 = (const float*)d_in[10];
    const float* b22 = (const float*)d_in[11];
    const float* W23 = (const float*)d_in[12];
    const float* b23 = (const float*)d_in[13];

    int N = in_sizes[0] / 128;
    int E = in_sizes[1] / 2;
    const int* src = ei;
    const int* dst = ei + E;

    float*   ps_dev; cudaGetSymbolAddress((void**)&ps_dev, g_ps);
    __half2* vh_dev; cudaGetSymbolAddress((void**)&vh_dev, g_vh);
    float*   h1_dev; cudaGetSymbolAddress((void**)&h1_dev, g_h1);
    int*     cnt_dev; cudaGetSymbolAddress((void**)&cnt_dev, g_cnt);

    // opt-in dynamic smem (80KB for K=128); host-side config, idempotent
    cudaFuncSetAttribute(k_gemm2, cudaFuncAttributeMaxDynamicSharedMemorySize, 80 * 1024);

    int gemm_blocks = (N + BM - 1) / BM;
    int agg_blocks = (int)(((long long)N * 32 + 255) / 256);
    size_t smem1 = (size_t)(2 * 128 * 64 + 2 * 16 * 128) * 4;  // K=128: 80KB
    size_t smem2 = (size_t)(2 * 64 * 64 + 2 * 16 * 128) * 4;   // K=64:  48KB

    // Side stream: CSR build overlapped with the layer-1 GEMM (fork/join off
    // the capture stream). Streams/events intentionally leaked (host-side only).
    cudaStream_t s2;
    cudaStreamCreateWithFlags(&s2, cudaStreamNonBlocking);
    cudaEvent_t evFork, evJoin;
    cudaEventCreateWithFlags(&evFork, cudaEventDisableTiming);
    cudaEventCreateWithFlags(&evJoin, cudaEventDisableTiming);

    cudaEventRecord(evFork, 0);
    cudaStreamWaitEvent(s2, evFork, 0);

    // ---- CSR build on s2 ----
    cudaMemsetAsync(cnt_dev, 0, (size_t)N * sizeof(int), s2);
    k_count<<<(E + 255) / 256, 256, 0, s2>>>(src, E);
    k_scan<<<1, 1024, 0, s2>>>(N, E);
    k_scatter<<<(E + 255) / 256, 256, 0, s2>>>(src, dst, E);

    // ---- layer-1 GEMM on main stream (independent of CSR) ----
    k_gemm2<<<gemm_blocks, 256, smem1>>>(h, N, 128, W11, b11, W12, W13, b13, ps_dev, vh_dev);

    cudaEventRecord(evJoin, s2);
    cudaStreamWaitEvent(0, evJoin, 0);

    // ---- layer 1 aggregation ----
    k_agg<<<agg_blocks, 256>>>(ps_dev, b12, h1_dev, N);

    // ---- layer 2 ----
    k_gemm2<<<gemm_blocks, 256, smem2>>>(h1_dev, N, 64, W21, b21, W22, W23, b23, ps_dev, vh_dev);
    k_agg<<<agg_blocks, 256>>>(ps_dev, b22, (float*)d_out, N);
}

// round 13
// speedup vs baseline: 1.0124x; 1.0124x over previous
#include <cuda_runtime.h>
#include <cuda_fp16.h>
#include <cuda_bf16.h>
#include <cstdint>
#include <math.h>

// Problem capacities (fixed by the dataset: N=100000, E=1600000)
#define NMAX 100096
#define EMAX 1600000

// -------- scratch (alloc-free: __device__ globals) --------
__device__ float   g_ps[NMAX];          // per-node edge-score scalar
__device__ __half2 g_vh[NMAX * 32];     // node values tanh(xWv^T+bv), fp16, 64 cols
__device__ float   g_h1[NMAX * 64];     // layer-1 output (fp32, feeds layer-2 GEMM)
__device__ float   g_ex[EMAX];          // exp(edge logit), CSR order
__device__ int     g_rowptr[NMAX + 1];
__device__ int     g_cnt[NMAX];
__device__ int     g_dstc[EMAX];

// -------------------- CSR build --------------------
__global__ void k_count(const int* __restrict__ src, int E) {
    int e = blockIdx.x * blockDim.x + threadIdx.x;
    if (e < E) atomicAdd(&g_cnt[src[e]], 1);
}

__global__ void k_scan(int N, int E) {
    __shared__ int sh[1024];
    int t = threadIdx.x;
    int chunk = (N + 1023) / 1024;
    int start = t * chunk;
    int end = min(start + chunk, N);
    int s = 0;
    for (int i = start; i < end; i++) s += g_cnt[i];
    sh[t] = s;
    __syncthreads();
    for (int off = 1; off < 1024; off <<= 1) {
        int v = 0;
        if (t >= off) v = sh[t - off];
        __syncthreads();
        if (t >= off) sh[t] += v;
        __syncthreads();
    }
    int run = (t == 0) ? 0 : sh[t - 1];
    for (int i = start; i < end; i++) {
        int c = g_cnt[i];
        g_rowptr[i] = run;
        g_cnt[i] = 0;
        run += c;
    }
    if (t == 1023) g_rowptr[N] = sh[1023];
}

__global__ void k_scatter(const int* __restrict__ src, const int* __restrict__ dst, int E) {
    int e = blockIdx.x * blockDim.x + threadIdx.x;
    if (e < E) {
        int s = src[e];
        int p = g_rowptr[s] + atomicAdd(&g_cnt[s], 1);
        g_dstc[p] = dst[e];
    }
}

// -------------------- tensor-core helpers --------------------
__device__ __forceinline__ void ldm_x4(uint32_t& r0, uint32_t& r1, uint32_t& r2, uint32_t& r3,
                                       uint32_t addr) {
    asm volatile("ldmatrix.sync.aligned.m8n8.x4.shared.b16 {%0,%1,%2,%3}, [%4];\n"
                 : "=r"(r0), "=r"(r1), "=r"(r2), "=r"(r3) : "r"(addr));
}
__device__ __forceinline__ void mma_bf16(float* d,
                                         uint32_t a0, uint32_t a1, uint32_t a2, uint32_t a3,
                                         uint32_t b0, uint32_t b1) {
    asm volatile("mma.sync.aligned.m16n8k16.row.col.f32.bf16.bf16.f32 "
                 "{%0,%1,%2,%3}, {%4,%5,%6,%7}, {%8,%9}, {%0,%1,%2,%3};\n"
                 : "+f"(d[0]), "+f"(d[1]), "+f"(d[2]), "+f"(d[3])
                 : "r"(a0), "r"(a1), "r"(a2), "r"(a3), "r"(b0), "r"(b1));
}

// -------------------- fused GEMM via bf16-split HMMA --------------------
// vh[N,32] (half2) = tanh(X[N,K] @ Wv^T + bv)
// ps[N]            = tanh(X[N,K] @ Wa^T + ba) · We
// Precision: x = hi + lo (bf16 each); C += xh·wh + xh·wl + xl·wh (fp32 accum).
// smem (bf16): Wa_hi[64][K+8] | Wa_lo | Wv_hi | Wv_lo | Xh[2][128][24] | Xl[2][128][24]
#define BM 128
#define BK 16

__global__ __launch_bounds__(256, 2) void k_gemm2(
    const float* __restrict__ X, int N, int K,
    const float* __restrict__ Wa, const float* __restrict__ ba,
    const float* __restrict__ We,
    const float* __restrict__ Wv, const float* __restrict__ bv,
    float* __restrict__ ps, __half2* __restrict__ vh)
{
    extern __shared__ __align__(16) char smraw[];
    __nv_bfloat16* sm = (__nv_bfloat16*)smraw;
    const int WP = K + 8;          // padded pitch (272B/144B row stride: conflict-free)
    const int WSZ = 64 * WP;       // one weight matrix (elems)
    __nv_bfloat16* Xh = sm + 4 * WSZ;          // [2][128][24]
    __nv_bfloat16* Xl = Xh + 2 * 128 * 24;

    int tid = threadIdx.x;
    int bm = blockIdx.x * BM;
    int warp = tid >> 5, lane = tid & 31;

    // ---- load + split weights into smem (once) ----
    int kq = K >> 2;
    for (int idx = tid; idx < 16 * K; idx += 256) {   // 64*K/4 float4 pairs
        int row = idx / kq;
        int k4 = (idx - row * kq) * 4;
        float4 qa = *(const float4*)&Wa[(size_t)row * K + k4];
        float4 qv = *(const float4*)&Wv[(size_t)row * K + k4];
        float va[4] = {qa.x, qa.y, qa.z, qa.w};
        float vv[4] = {qv.x, qv.y, qv.z, qv.w};
        __nv_bfloat16 ah[4], al[4], vh4[4], vl[4];
        #pragma unroll
        for (int u = 0; u < 4; u++) {
            ah[u] = __float2bfloat16(va[u]);
            al[u] = __float2bfloat16(va[u] - __bfloat162float(ah[u]));
            vh4[u] = __float2bfloat16(vv[u]);
            vl[u] = __float2bfloat16(vv[u] - __bfloat162float(vh4[u]));
        }
        *(uint2*)&sm[0 * WSZ + row * WP + k4] = *(uint2*)ah;
        *(uint2*)&sm[1 * WSZ + row * WP + k4] = *(uint2*)al;
        *(uint2*)&sm[2 * WSZ + row * WP + k4] = *(uint2*)vh4;
        *(uint2*)&sm[3 * WSZ + row * WP + k4] = *(uint2*)vl;
    }

    // ---- X tile loader indices: thread -> (row, k-half) ----
    int xrow = tid >> 1;            // 0..127
    int xkh = (tid & 1) * 8;        // 0 or 8
    float4 pf0, pf1;

    // prefetch tile 0
    {
        int gm = bm + xrow;
        if (gm < N) {
            pf0 = *(const float4*)&X[(size_t)gm * K + xkh];
            pf1 = *(const float4*)&X[(size_t)gm * K + xkh + 4];
        } else { pf0 = make_float4(0,0,0,0); pf1 = make_float4(0,0,0,0); }
    }
    // store tile 0 into buffer 0
    {
        float v8[8] = {pf0.x, pf0.y, pf0.z, pf0.w, pf1.x, pf1.y, pf1.z, pf1.w};
        __nv_bfloat16 h8[8], l8[8];
        #pragma unroll
        for (int u = 0; u < 8; u++) {
            h8[u] = __float2bfloat16(v8[u]);
            l8[u] = __float2bfloat16(v8[u] - __bfloat162float(h8[u]));
        }
        *(uint4*)&Xh[xrow * 24 + xkh] = *(uint4*)h8;
        *(uint4*)&Xl[xrow * 24 + xkh] = *(uint4*)l8;
    }
    __syncthreads();

    // ---- per-lane smem byte addresses ----
    uint32_t smbase = (uint32_t)__cvta_generic_to_shared(sm);
    int g = lane >> 3, li = lane & 7;
    int wm = warp * 16;
    // A: matrices [m0-7,k0-7][m8-15,k0-7][m0-7,k8-15][m8-15,k8-15]
    uint32_t aAh = smbase + (uint32_t)(8 * WSZ) /*bytes of 4 weight mats*/
                 + (uint32_t)(((wm + (g & 1) * 8 + li) * 24 + (g >> 1) * 8) * 2);
    const uint32_t XBUF = 128 * 24 * 2;          // 6144B per buffer
    const uint32_t HL = 2 * XBUF;                // Xh -> Xl distance
    // B: matrices [n,k0-7]hi [n,k8-15]hi [n,k0-7]lo [n,k8-15]lo
    uint32_t bOff = (uint32_t)((li * WP + (g & 1) * 8 + (g >> 1) * WSZ) * 2);
    const uint32_t offWv = (uint32_t)(2 * WSZ * 2);
    const uint32_t ntStep = (uint32_t)(16 * WP); // 8 n-rows * WP * 2B

    float accA[8][4] = {};
    float accV[8][4] = {};

    int T = K / BK;
    for (int t = 0; t < T; t++) {
        if (t + 1 < T) {
            int gm = bm + xrow;
            int koff = (t + 1) * BK + xkh;
            if (gm < N) {
                pf0 = *(const float4*)&X[(size_t)gm * K + koff];
                pf1 = *(const float4*)&X[(size_t)gm * K + koff + 4];
            } else { pf0 = make_float4(0,0,0,0); pf1 = make_float4(0,0,0,0); }
        }

        uint32_t bufo = (uint32_t)((t & 1) * XBUF);
        uint32_t a0, a1, a2, a3, l0, l1, l2, l3;
        ldm_x4(a0, a1, a2, a3, aAh + bufo);
        ldm_x4(l0, l1, l2, l3, aAh + bufo + HL);
        uint32_t wk = smbase + bOff + (uint32_t)(t * 32);
        #pragma unroll
        for (int nt = 0; nt < 8; nt++) {
            uint32_t b0, b1, b2, b3;
            ldm_x4(b0, b1, b2, b3, wk + nt * ntStep);
            mma_bf16(accA[nt], a0, a1, a2, a3, b0, b1);   // hi*hi
            mma_bf16(accA[nt], a0, a1, a2, a3, b2, b3);   // hi*lo
            mma_bf16(accA[nt], l0, l1, l2, l3, b0, b1);   // lo*hi
            ldm_x4(b0, b1, b2, b3, wk + offWv + nt * ntStep);
            mma_bf16(accV[nt], a0, a1, a2, a3, b0, b1);
            mma_bf16(accV[nt], a0, a1, a2, a3, b2, b3);
            mma_bf16(accV[nt], l0, l1, l2, l3, b0, b1);
        }

        if (t + 1 < T) {
            float v8[8] = {pf0.x, pf0.y, pf0.z, pf0.w, pf1.x, pf1.y, pf1.z, pf1.w};
            __nv_bfloat16 h8[8], l8[8];
            #pragma unroll
            for (int u = 0; u < 8; u++) {
                h8[u] = __float2bfloat16(v8[u]);
                l8[u] = __float2bfloat16(v8[u] - __bfloat162float(h8[u]));
            }
            int boff = ((t + 1) & 1) * 128 * 24;
            *(uint4*)&Xh[boff + xrow * 24 + xkh] = *(uint4*)h8;
            *(uint4*)&Xl[boff + xrow * 24 + xkh] = *(uint4*)l8;
            __syncthreads();
        }
    }

    // ---- epilogue: tanh, fp16 v pack, ps reduction ----
    int r0 = bm + wm + (lane >> 2);
    int r1 = r0 + 8;
    int cq = (lane & 3) * 2;
    float psum0 = 0.f, psum1 = 0.f;
    #pragma unroll
    for (int nt = 0; nt < 8; nt++) {
        int c0 = nt * 8 + cq;
        float we0 = We[c0], we1 = We[c0 + 1];
        float ba0 = ba[c0], ba1 = ba[c0 + 1];
        float bv0 = bv[c0], bv1 = bv[c0 + 1];
        psum0 += tanhf(accA[nt][0] + ba0) * we0 + tanhf(accA[nt][1] + ba1) * we1;
        psum1 += tanhf(accA[nt][2] + ba0) * we0 + tanhf(accA[nt][3] + ba1) * we1;
        int hcol = nt * 4 + (lane & 3);
        if (r0 < N)
            vh[(size_t)r0 * 32 + hcol] =
                __floats2half2_rn(tanhf(accV[nt][0] + bv0), tanhf(accV[nt][1] + bv1));
        if (r1 < N)
            vh[(size_t)r1 * 32 + hcol] =
                __floats2half2_rn(tanhf(accV[nt][2] + bv0), tanhf(accV[nt][3] + bv1));
    }
    psum0 += __shfl_xor_sync(0xffffffffu, psum0, 1);
    psum0 += __shfl_xor_sync(0xffffffffu, psum0, 2);
    psum1 += __shfl_xor_sync(0xffffffffu, psum1, 1);
    psum1 += __shfl_xor_sync(0xffffffffu, psum1, 2);
    if ((lane & 3) == 0) {
        if (r0 < N) ps[r0] = psum0;
        if (r1 < N) ps[r1] = psum1;
    }
}

// ---------- fused softmax + aggregation + row std-norm (warp per node) ----------
__global__ __launch_bounds__(256) void k_agg(
    const float* __restrict__ ps, const float* __restrict__ be,
    float* __restrict__ Out, int N)
{
    int wid = (blockIdx.x * blockDim.x + threadIdx.x) >> 5;
    int lane = threadIdx.x & 31;
    if (wid >= N) return;

    int r0 = g_rowptr[wid];
    int r1 = g_rowptr[wid + 1];
    float pr = ps[wid] + be[0];

    // pass 1: edge logits -> exp, softmax denominator
    float sum = 0.f;
    for (int p = r0 + lane; p < r1; p += 32) {
        int d = g_dstc[p];
        float e = expf(tanhf(pr + ps[d]));   // |tanh|<1 -> no max-subtraction needed
        g_ex[p] = e;
        sum += e;
    }
    #pragma unroll
    for (int off = 16; off > 0; off >>= 1) sum += __shfl_xor_sync(0xffffffffu, sum, off);
    float inv = 1.0f / sum;

    // pass 2: 4 edges per warp-iteration, uint4 row gathers
    int g = lane >> 3;    // 0..3  edge within group-of-4
    int c = lane & 7;     // 0..7  column chunk (8 cols)
    const uint4* v4 = (const uint4*)g_vh;    // v row = 8 uint4 (64 fp16)
    float acc[8] = {};
    for (int base = r0; base < r1; base += 4) {
        int p = base + g;
        float att = 0.f;
        int d = 0;
        if (p < r1) {
            att = g_ex[p] * inv;
            d = g_dstc[p];
        }
        uint4 q = v4[(size_t)d * 8 + c];
        const __half2* hq = (const __half2*)&q;
        #pragma unroll
        for (int t = 0; t < 4; t++) {
            float2 f = __half22float2(hq[t]);
            acc[2 * t]     = fmaf(att, f.x, acc[2 * t]);
            acc[2 * t + 1] = fmaf(att, f.y, acc[2 * t + 1]);
        }
    }
    #pragma unroll
    for (int t = 0; t < 8; t++) {
        acc[t] += __shfl_xor_sync(0xffffffffu, acc[t], 8);
        acc[t] += __shfl_xor_sync(0xffffffffu, acc[t], 16);
    }

    float s = 0.f;
    #pragma unroll
    for (int t = 0; t < 8; t++) s += acc[t];
    #pragma unroll
    for (int off = 4; off > 0; off >>= 1) s += __shfl_xor_sync(0xffffffffu, s, off);
    float mean = s * (1.0f / 64.0f);
    float q2 = 0.f;
    #pragma unroll
    for (int t = 0; t < 8; t++) { float dq = acc[t] - mean; q2 = fmaf(dq, dq, q2); }
    #pragma unroll
    for (int off = 4; off > 0; off >>= 1) q2 += __shfl_xor_sync(0xffffffffu, q2, off);
    float inv_std = rsqrtf(q2 * (1.0f / 63.0f));

    if (g < 2) {
        float4 o;
        o.x = acc[g * 4 + 0] * inv_std;
        o.y = acc[g * 4 + 1] * inv_std;
        o.z = acc[g * 4 + 2] * inv_std;
        o.w = acc[g * 4 + 3] * inv_std;
        *(float4*)&Out[(size_t)wid * 64 + c * 8 + g * 4] = o;
    }
}

// -------------------- launch --------------------
extern "C" void kernel_launch(void* const* d_in, const int* in_sizes, int n_in,
                              void* d_out, int out_size)
{
    const float* h   = (const float*)d_in[0];
    const int*   ei  = (const int*)d_in[1];
    const float* W11 = (const float*)d_in[2];
    const float* b11 = (const float*)d_in[3];
    const float* W12 = (const float*)d_in[4];
    const float* b12 = (const float*)d_in[5];
    const float* W13 = (const float*)d_in[6];
    const float* b13 = (const float*)d_in[7];
    const float* W21 = (const float*)d_in[8];
    const float* b21 = (const float*)d_in[9];
    const float* W22 = (const float*)d_in[10];
    const float* b22 = (const float*)d_in[11];
    const float* W23 = (const float*)d_in[12];
    const float* b23 = (const float*)d_in[13];

    int N = in_sizes[0] / 128;
    int E = in_sizes[1] / 2;
    const int* src = ei;
    const int* dst = ei + E;

    float*   ps_dev; cudaGetSymbolAddress((void**)&ps_dev, g_ps);
    __half2* vh_dev; cudaGetSymbolAddress((void**)&vh_dev, g_vh);
    float*   h1_dev; cudaGetSymbolAddress((void**)&h1_dev, g_h1);
    int*     cnt_dev; cudaGetSymbolAddress((void**)&cnt_dev, g_cnt);

    // smem: 4 weight mats (bf16, pitch K+8) + 4 X buffers (2 buf x hi/lo, 128x24 bf16)
    size_t smem1 = (size_t)(4 * 64 * (128 + 8) + 4 * 128 * 24) * 2;  // K=128: 94208B
    size_t smem2 = (size_t)(4 * 64 * (64 + 8) + 4 * 128 * 24) * 2;   // K=64:  61440B
    cudaFuncSetAttribute(k_gemm2, cudaFuncAttributeMaxDynamicSharedMemorySize, (int)smem1);

    int gemm_blocks = (N + BM - 1) / BM;
    int agg_blocks = (int)(((long long)N * 32 + 255) / 256);

    // Side stream: CSR build overlapped with the layer-1 GEMM (fork/join off
    // the capture stream). Streams/events intentionally leaked (host-side only).
    cudaStream_t s2;
    cudaStreamCreateWithFlags(&s2, cudaStreamNonBlocking);
    cudaEvent_t evFork, evJoin;
    cudaEventCreateWithFlags(&evFork, cudaEventDisableTiming);
    cudaEventCreateWithFlags(&evJoin, cudaEventDisableTiming);

    cudaEventRecord(evFork, 0);
    cudaStreamWaitEvent(s2, evFork, 0);

    // ---- CSR build on s2 ----
    cudaMemsetAsync(cnt_dev, 0, (size_t)N * sizeof(int), s2);
    k_count<<<(E + 255) / 256, 256, 0, s2>>>(src, E);
    k_scan<<<1, 1024, 0, s2>>>(N, E);
    k_scatter<<<(E + 255) / 256, 256, 0, s2>>>(src, dst, E);

    // ---- layer-1 GEMM on main stream (independent of CSR) ----
    k_gemm2<<<gemm_blocks, 256, smem1>>>(h, N, 128, W11, b11, W12, W13, b13, ps_dev, vh_dev);

    cudaEventRecord(evJoin, s2);
    cudaStreamWaitEvent(0, evJoin, 0);

    // ---- layer 1 aggregation ----
    k_agg<<<agg_blocks, 256>>>(ps_dev, b12, h1_dev, N);

    // ---- layer 2 ----
    k_gemm2<<<gemm_blocks, 256, smem2>>>(h1_dev, N, 64, W21, b21, W22, W23, b23, ps_dev, vh_dev);
    k_agg<<<agg_blocks, 256>>>(ps_dev, b22, (float*)d_out, N);
}

// round 16
// speedup vs baseline: 1.0184x; 1.0059x over previous
#include <cuda_runtime.h>
#include <cuda_fp16.h>
#include <cuda_bf16.h>
#include <cstdint>
#include <math.h>

// Problem capacities (fixed by the dataset: N=100000, E=1600000)
#define NMAX 100096
#define EMAX 1600000

// -------- scratch (alloc-free: __device__ globals) --------
__device__ float   g_ps[NMAX];          // per-node edge-score scalar
__device__ __half2 g_vh[NMAX * 32];     // node values tanh(xWv^T+bv), fp16, 64 cols
__device__ float   g_h1[NMAX * 64];     // layer-1 output (fp32, feeds layer-2 GEMM)
__device__ float   g_ex[EMAX];          // exp(edge logit) — fallback path only
__device__ int     g_rowptr[NMAX + 1];
__device__ int     g_cnt[NMAX];
__device__ int     g_dstc[EMAX];

// -------------------- CSR build (R7/R13-proven) --------------------
__global__ void k_count(const int* __restrict__ src, int E) {
    int e = blockIdx.x * blockDim.x + threadIdx.x;
    if (e < E) atomicAdd(&g_cnt[src[e]], 1);
}

__global__ void k_scan(int N, int E) {
    __shared__ int sh[1024];
    int t = threadIdx.x;
    int chunk = (N + 1023) / 1024;
    int start = t * chunk;
    int end = min(start + chunk, N);
    int s = 0;
    for (int i = start; i < end; i++) s += g_cnt[i];
    sh[t] = s;
    __syncthreads();
    for (int off = 1; off < 1024; off <<= 1) {
        int v = 0;
        if (t >= off) v = sh[t - off];
        __syncthreads();
        if (t >= off) sh[t] += v;
        __syncthreads();
    }
    int run = (t == 0) ? 0 : sh[t - 1];
    for (int i = start; i < end; i++) {
        int c = g_cnt[i];
        g_rowptr[i] = run;
        g_cnt[i] = 0;
        run += c;
    }
    if (t == 1023) g_rowptr[N] = sh[1023];
}

__global__ void k_scatter(const int* __restrict__ src, const int* __restrict__ dst, int E) {
    int e = blockIdx.x * blockDim.x + threadIdx.x;
    if (e < E) {
        int s = src[e];
        int p = g_rowptr[s] + atomicAdd(&g_cnt[s], 1);
        g_dstc[p] = dst[e];
    }
}

// -------------------- tensor-core helpers (R13-proven) --------------------
__device__ __forceinline__ void ldm_x4(uint32_t& r0, uint32_t& r1, uint32_t& r2, uint32_t& r3,
                                       uint32_t addr) {
    asm volatile("ldmatrix.sync.aligned.m8n8.x4.shared.b16 {%0,%1,%2,%3}, [%4];\n"
                 : "=r"(r0), "=r"(r1), "=r"(r2), "=r"(r3) : "r"(addr));
}
__device__ __forceinline__ void mma_bf16(float* d,
                                         uint32_t a0, uint32_t a1, uint32_t a2, uint32_t a3,
                                         uint32_t b0, uint32_t b1) {
    asm volatile("mma.sync.aligned.m16n8k16.row.col.f32.bf16.bf16.f32 "
                 "{%0,%1,%2,%3}, {%4,%5,%6,%7}, {%8,%9}, {%0,%1,%2,%3};\n"
                 : "+f"(d[0]), "+f"(d[1]), "+f"(d[2]), "+f"(d[3])
                 : "r"(a0), "r"(a1), "r"(a2), "r"(a3), "r"(b0), "r"(b1));
}

// -------------------- fused GEMM via bf16-split HMMA (R13-proven) ----------
#define BM 128
#define BK 16

__global__ __launch_bounds__(256, 2) void k_gemm2(
    const float* __restrict__ X, int N, int K,
    const float* __restrict__ Wa, const float* __restrict__ ba,
    const float* __restrict__ We,
    const float* __restrict__ Wv, const float* __restrict__ bv,
    float* __restrict__ ps, __half2* __restrict__ vh)
{
    extern __shared__ __align__(16) char smraw[];
    __nv_bfloat16* sm = (__nv_bfloat16*)smraw;
    const int WP = K + 8;
    const int WSZ = 64 * WP;
    __nv_bfloat16* Xh = sm + 4 * WSZ;
    __nv_bfloat16* Xl = Xh + 2 * 128 * 24;

    int tid = threadIdx.x;
    int bm = blockIdx.x * BM;
    int warp = tid >> 5, lane = tid & 31;

    int kq = K >> 2;
    for (int idx = tid; idx < 16 * K; idx += 256) {
        int row = idx / kq;
        int k4 = (idx - row * kq) * 4;
        float4 qa = *(const float4*)&Wa[(size_t)row * K + k4];
        float4 qv = *(const float4*)&Wv[(size_t)row * K + k4];
        float va[4] = {qa.x, qa.y, qa.z, qa.w};
        float vv[4] = {qv.x, qv.y, qv.z, qv.w};
        __nv_bfloat16 ah[4], al[4], vh4[4], vl[4];
        #pragma unroll
        for (int u = 0; u < 4; u++) {
            ah[u] = __float2bfloat16(va[u]);
            al[u] = __float2bfloat16(va[u] - __bfloat162float(ah[u]));
            vh4[u] = __float2bfloat16(vv[u]);
            vl[u] = __float2bfloat16(vv[u] - __bfloat162float(vh4[u]));
        }
        *(uint2*)&sm[0 * WSZ + row * WP + k4] = *(uint2*)ah;
        *(uint2*)&sm[1 * WSZ + row * WP + k4] = *(uint2*)al;
        *(uint2*)&sm[2 * WSZ + row * WP + k4] = *(uint2*)vh4;
        *(uint2*)&sm[3 * WSZ + row * WP + k4] = *(uint2*)vl;
    }

    int xrow = tid >> 1;
    int xkh = (tid & 1) * 8;
    float4 pf0, pf1;

    {
        int gm = bm + xrow;
        if (gm < N) {
            pf0 = *(const float4*)&X[(size_t)gm * K + xkh];
            pf1 = *(const float4*)&X[(size_t)gm * K + xkh + 4];
        } else { pf0 = make_float4(0,0,0,0); pf1 = make_float4(0,0,0,0); }
    }
    {
        float v8[8] = {pf0.x, pf0.y, pf0.z, pf0.w, pf1.x, pf1.y, pf1.z, pf1.w};
        __nv_bfloat16 h8[8], l8[8];
        #pragma unroll
        for (int u = 0; u < 8; u++) {
            h8[u] = __float2bfloat16(v8[u]);
            l8[u] = __float2bfloat16(v8[u] - __bfloat162float(h8[u]));
        }
        *(uint4*)&Xh[xrow * 24 + xkh] = *(uint4*)h8;
        *(uint4*)&Xl[xrow * 24 + xkh] = *(uint4*)l8;
    }
    __syncthreads();

    uint32_t smbase = (uint32_t)__cvta_generic_to_shared(sm);
    int g = lane >> 3, li = lane & 7;
    int wm = warp * 16;
    uint32_t aAh = smbase + (uint32_t)(8 * WSZ)
                 + (uint32_t)(((wm + (g & 1) * 8 + li) * 24 + (g >> 1) * 8) * 2);
    const uint32_t XBUF = 128 * 24 * 2;
    const uint32_t HL = 2 * XBUF;
    uint32_t bOff = (uint32_t)((li * WP + (g & 1) * 8 + (g >> 1) * WSZ) * 2);
    const uint32_t offWv = (uint32_t)(2 * WSZ * 2);
    const uint32_t ntStep = (uint32_t)(16 * WP);

    float accA[8][4] = {};
    float accV[8][4] = {};

    int T = K / BK;
    for (int t = 0; t < T; t++) {
        if (t + 1 < T) {
            int gm = bm + xrow;
            int koff = (t + 1) * BK + xkh;
            if (gm < N) {
                pf0 = *(const float4*)&X[(size_t)gm * K + koff];
                pf1 = *(const float4*)&X[(size_t)gm * K + koff + 4];
            } else { pf0 = make_float4(0,0,0,0); pf1 = make_float4(0,0,0,0); }
        }

        uint32_t bufo = (uint32_t)((t & 1) * XBUF);
        uint32_t a0, a1, a2, a3, l0, l1, l2, l3;
        ldm_x4(a0, a1, a2, a3, aAh + bufo);
        ldm_x4(l0, l1, l2, l3, aAh + bufo + HL);
        uint32_t wk = smbase + bOff + (uint32_t)(t * 32);
        #pragma unroll
        for (int nt = 0; nt < 8; nt++) {
            uint32_t b0, b1, b2, b3;
            ldm_x4(b0, b1, b2, b3, wk + nt * ntStep);
            mma_bf16(accA[nt], a0, a1, a2, a3, b0, b1);
            mma_bf16(accA[nt], a0, a1, a2, a3, b2, b3);
            mma_bf16(accA[nt], l0, l1, l2, l3, b0, b1);
            ldm_x4(b0, b1, b2, b3, wk + offWv + nt * ntStep);
            mma_bf16(accV[nt], a0, a1, a2, a3, b0, b1);
            mma_bf16(accV[nt], a0, a1, a2, a3, b2, b3);
            mma_bf16(accV[nt], l0, l1, l2, l3, b0, b1);
        }

        if (t + 1 < T) {
            float v8[8] = {pf0.x, pf0.y, pf0.z, pf0.w, pf1.x, pf1.y, pf1.z, pf1.w};
            __nv_bfloat16 h8[8], l8[8];
            #pragma unroll
            for (int u = 0; u < 8; u++) {
                h8[u] = __float2bfloat16(v8[u]);
                l8[u] = __float2bfloat16(v8[u] - __bfloat162float(h8[u]));
            }
            int boff = ((t + 1) & 1) * 128 * 24;
            *(uint4*)&Xh[boff + xrow * 24 + xkh] = *(uint4*)h8;
            *(uint4*)&Xl[boff + xrow * 24 + xkh] = *(uint4*)l8;
            __syncthreads();
        }
    }

    int r0 = bm + wm + (lane >> 2);
    int r1 = r0 + 8;
    int cq = (lane & 3) * 2;
    float psum0 = 0.f, psum1 = 0.f;
    #pragma unroll
    for (int nt = 0; nt < 8; nt++) {
        int c0 = nt * 8 + cq;
        float we0 = We[c0], we1 = We[c0 + 1];
        float ba0 = ba[c0], ba1 = ba[c0 + 1];
        float bv0 = bv[c0], bv1 = bv[c0 + 1];
        psum0 += tanhf(accA[nt][0] + ba0) * we0 + tanhf(accA[nt][1] + ba1) * we1;
        psum1 += tanhf(accA[nt][2] + ba0) * we0 + tanhf(accA[nt][3] + ba1) * we1;
        int hcol = nt * 4 + (lane & 3);
        if (r0 < N)
            vh[(size_t)r0 * 32 + hcol] =
                __floats2half2_rn(tanhf(accV[nt][0] + bv0), tanhf(accV[nt][1] + bv1));
        if (r1 < N)
            vh[(size_t)r1 * 32 + hcol] =
                __floats2half2_rn(tanhf(accV[nt][2] + bv0), tanhf(accV[nt][3] + bv1));
    }
    psum0 += __shfl_xor_sync(0xffffffffu, psum0, 1);
    psum0 += __shfl_xor_sync(0xffffffffu, psum0, 2);
    psum1 += __shfl_xor_sync(0xffffffffu, psum1, 1);
    psum1 += __shfl_xor_sync(0xffffffffu, psum1, 2);
    if ((lane & 3) == 0) {
        if (r0 < N) ps[r0] = psum0;
        if (r1 < N) ps[r1] = psum1;
    }
}

// ---------- fused softmax + aggregation + row std-norm (R7-proven) ----------
__global__ __launch_bounds__(256) void k_agg(
    const float* __restrict__ ps, const float* __restrict__ be,
    float* __restrict__ Out, int N)
{
    int wid = (blockIdx.x * blockDim.x + threadIdx.x) >> 5;
    int lane = threadIdx.x & 31;
    if (wid >= N) return;

    int r0 = g_rowptr[wid];
    int r1 = g_rowptr[wid + 1];
    int deg = r1 - r0;
    float pr = ps[wid] + be[0];

    int g = lane >> 3;    // 0..3  edge within group-of-4
    int c = lane & 7;     // 0..7  column chunk (8 cols)
    const uint4* v4 = (const uint4*)g_vh;    // v row = 8 uint4 (64 fp16)
    float acc[8] = {};

    if (deg <= 32) {
        // ---- register-resident softmax: one edge per lane ----
        float ex = 0.f;
        int d = 0;
        if (lane < deg) {
            d = g_dstc[r0 + lane];
            ex = expf(tanhf(pr + ps[d]));   // |tanh|<1 -> safe without max-sub
        }
        float sum = ex;
        #pragma unroll
        for (int off = 16; off > 0; off >>= 1) sum += __shfl_xor_sync(0xffffffffu, sum, off);
        float att = ex * (1.0f / sum);      // lanes >= deg hold att = 0

        for (int i0 = 0; i0 < deg; i0 += 8) {
            int j0 = i0 + g;
            int j1 = i0 + 4 + g;
            j0 &= 31; j1 &= 31;              // safety clamp (att of those lanes is 0 anyway)
            float a0 = __shfl_sync(0xffffffffu, att, j0);
            int   d0 = __shfl_sync(0xffffffffu, d,   j0);
            float a1 = __shfl_sync(0xffffffffu, att, j1);
            int   d1 = __shfl_sync(0xffffffffu, d,   j1);
            uint4 q0 = v4[(size_t)d0 * 8 + c];
            uint4 q1 = v4[(size_t)d1 * 8 + c];
            const __half2* h0 = (const __half2*)&q0;
            const __half2* h1 = (const __half2*)&q1;
            #pragma unroll
            for (int t = 0; t < 4; t++) {
                float2 f0 = __half22float2(h0[t]);
                float2 f1 = __half22float2(h1[t]);
                acc[2 * t]     = fmaf(a0, f0.x, acc[2 * t]);
                acc[2 * t + 1] = fmaf(a0, f0.y, acc[2 * t + 1]);
                acc[2 * t]     = fmaf(a1, f1.x, acc[2 * t]);
                acc[2 * t + 1] = fmaf(a1, f1.y, acc[2 * t + 1]);
            }
        }
    } else {
        // ---- fallback (rare: deg > 32): two-pass via g_ex ----
        float sum = 0.f;
        for (int p = r0 + lane; p < r1; p += 32) {
            int d = g_dstc[p];
            float e = expf(tanhf(pr + ps[d]));
            g_ex[p] = e;
            sum += e;
        }
        #pragma unroll
        for (int off = 16; off > 0; off >>= 1) sum += __shfl_xor_sync(0xffffffffu, sum, off);
        float inv = 1.0f / sum;

        for (int base = r0; base < r1; base += 4) {
            int p = base + g;
            float att = 0.f;
            int d = 0;
            if (p < r1) {
                att = g_ex[p] * inv;
                d = g_dstc[p];
            }
            uint4 q = v4[(size_t)d * 8 + c];
            const __half2* hq = (const __half2*)&q;
            #pragma unroll
            for (int t = 0; t < 4; t++) {
                float2 f = __half22float2(hq[t]);
                acc[2 * t]     = fmaf(att, f.x, acc[2 * t]);
                acc[2 * t + 1] = fmaf(att, f.y, acc[2 * t + 1]);
            }
        }
    }

    // reduce across the 4 edge-groups (lane bits 3,4)
    #pragma unroll
    for (int t = 0; t < 8; t++) {
        acc[t] += __shfl_xor_sync(0xffffffffu, acc[t], 8);
        acc[t] += __shfl_xor_sync(0xffffffffu, acc[t], 16);
    }

    // row stats over 64 cols: butterfly across c bits only (g copies identical)
    float s = 0.f;
    #pragma unroll
    for (int t = 0; t < 8; t++) s += acc[t];
    #pragma unroll
    for (int off = 4; off > 0; off >>= 1) s += __shfl_xor_sync(0xffffffffu, s, off);
    float mean = s * (1.0f / 64.0f);
    float q2 = 0.f;
    #pragma unroll
    for (int t = 0; t < 8; t++) { float dq = acc[t] - mean; q2 = fmaf(dq, dq, q2); }
    #pragma unroll
    for (int off = 4; off > 0; off >>= 1) q2 += __shfl_xor_sync(0xffffffffu, q2, off);
    float inv_std = rsqrtf(q2 * (1.0f / 63.0f));

    if (g < 2) {
        float4 o;
        o.x = acc[g * 4 + 0] * inv_std;
        o.y = acc[g * 4 + 1] * inv_std;
        o.z = acc[g * 4 + 2] * inv_std;
        o.w = acc[g * 4 + 3] * inv_std;
        *(float4*)&Out[(size_t)wid * 64 + c * 8 + g * 4] = o;
    }
}

// -------------------- launch --------------------
extern "C" void kernel_launch(void* const* d_in, const int* in_sizes, int n_in,
                              void* d_out, int out_size)
{
    const float* h   = (const float*)d_in[0];
    const int*   ei  = (const int*)d_in[1];
    const float* W11 = (const float*)d_in[2];
    const float* b11 = (const float*)d_in[3];
    const float* W12 = (const float*)d_in[4];
    const float* b12 = (const float*)d_in[5];
    const float* W13 = (const float*)d_in[6];
    const float* b13 = (const float*)d_in[7];
    const float* W21 = (const float*)d_in[8];
    const float* b21 = (const float*)d_in[9];
    const float* W22 = (const float*)d_in[10];
    const float* b22 = (const float*)d_in[11];
    const float* W23 = (const float*)d_in[12];
    const float* b23 = (const float*)d_in[13];

    int N = in_sizes[0] / 128;
    int E = in_sizes[1] / 2;
    const int* src = ei;
    const int* dst = ei + E;

    float*   ps_dev; cudaGetSymbolAddress((void**)&ps_dev, g_ps);
    __half2* vh_dev; cudaGetSymbolAddress((void**)&vh_dev, g_vh);
    float*   h1_dev; cudaGetSymbolAddress((void**)&h1_dev, g_h1);
    int*     cnt_dev; cudaGetSymbolAddress((void**)&cnt_dev, g_cnt);

    size_t smem1 = (size_t)(4 * 64 * (128 + 8) + 4 * 128 * 24) * 2;  // K=128
    size_t smem2 = (size_t)(4 * 64 * (64 + 8) + 4 * 128 * 24) * 2;   // K=64
    cudaFuncSetAttribute(k_gemm2, cudaFuncAttributeMaxDynamicSharedMemorySize, (int)smem1);

    int gemm_blocks = (N + BM - 1) / BM;
    int edge_blocks = (E + 255) / 256;
    int agg_blocks = (int)(((long long)N * 32 + 255) / 256);

    // Side stream: CSR build overlapped with the layer-1 GEMM (fork/join off
    // the capture stream). Streams/events intentionally leaked (host-side only).
    cudaStream_t s2;
    cudaStreamCreateWithFlags(&s2, cudaStreamNonBlocking);
    cudaEvent_t evFork, evJoin;
    cudaEventCreateWithFlags(&evFork, cudaEventDisableTiming);
    cudaEventCreateWithFlags(&evJoin, cudaEventDisableTiming);

    cudaEventRecord(evFork, 0);
    cudaStreamWaitEvent(s2, evFork, 0);

    // ---- CSR build on s2 ----
    cudaMemsetAsync(cnt_dev, 0, (size_t)N * sizeof(int), s2);
    k_count<<<edge_blocks, 256, 0, s2>>>(src, E);
    k_scan<<<1, 1024, 0, s2>>>(N, E);
    k_scatter<<<edge_blocks, 256, 0, s2>>>(src, dst, E);

    // ---- layer-1 GEMM on main stream (independent of CSR) ----
    k_gemm2<<<gemm_blocks, 256, smem1>>>(h, N, 128, W11, b11, W12, W13, b13, ps_dev, vh_dev);

    cudaEventRecord(evJoin, s2);
    cudaStreamWaitEvent(0, evJoin, 0);

    // ---- layer 1 aggregation ----
    k_agg<<<agg_blocks, 256>>>(ps_dev, b12, h1_dev, N);

    // ---- layer 2 ----
    k_gemm2<<<gemm_blocks, 256, smem2>>>(h1_dev, N, 64, W21, b21, W22, W23, b23, ps_dev, vh_dev);
    k_agg<<<agg_blocks, 256>>>(ps_dev, b22, (float*)d_out, N);
}

// round 17
// speedup vs baseline: 1.8762x; 1.8424x over previous
#include <cuda_runtime.h>
#include <cuda_fp16.h>
#include <cuda_bf16.h>
#include <cstdint>
#include <math.h>

// Problem capacities (fixed by the dataset: N=100000, E=1600000)
#define NMAX 100096
#define EMAX 1600000

// -------- scratch (alloc-free: __device__ globals) --------
__device__ float   g_ps[NMAX];          // per-node edge-score scalar
__device__ __half2 g_vh[NMAX * 32];     // node values tanh(xWv^T+bv), fp16, 64 cols
__device__ float   g_h1[NMAX * 64];     // layer-1 output (fp32, feeds layer-2 GEMM)
__device__ float   g_ex[EMAX];          // exp(edge logit), CSR order
__device__ int     g_rowptr[NMAX + 1];
__device__ int     g_cnt[NMAX];
__device__ int     g_bsum[132];         // block sums for the parallel scan
__device__ int     g_srcc[EMAX];        // CSR src (row of each slot)
__device__ int     g_dstc[EMAX];        // CSR dst

// -------------------- CSR build --------------------
__global__ void k_count(const int* __restrict__ src, int E) {
    int e = blockIdx.x * blockDim.x + threadIdx.x;
    if (e < E) atomicAdd(&g_cnt[src[e]], 1);
}

// parallel exclusive scan, stage 1: per-block Hillis-Steele over 1024 elems
#define SCAN_B 1024
__global__ void k_scan1(int N) {
    __shared__ int sh[SCAN_B];
    int tid = threadIdx.x;
    int i = blockIdx.x * SCAN_B + tid;
    int v = (i < N) ? g_cnt[i] : 0;
    sh[tid] = v;
    __syncthreads();
    for (int off = 1; off < SCAN_B; off <<= 1) {
        int x = sh[tid];
        int t = (tid >= off) ? sh[tid - off] : 0;
        __syncthreads();
        sh[tid] = x + t;
        __syncthreads();
    }
    int incl = sh[tid];
    if (i < N) g_rowptr[i] = incl - v;            // block-local exclusive
    if (tid == SCAN_B - 1) g_bsum[blockIdx.x] = incl;  // block total
}

// stage 2: scan the <=128 block totals (one block)
__global__ void k_scan2(int NB) {
    __shared__ int sh[128];
    int tid = threadIdx.x;
    int v = (tid < NB) ? g_bsum[tid] : 0;
    sh[tid] = v;
    __syncthreads();
    for (int off = 1; off < 128; off <<= 1) {
        int x = sh[tid];
        int t = (tid >= off) ? sh[tid - off] : 0;
        __syncthreads();
        sh[tid] = x + t;
        __syncthreads();
    }
    if (tid < NB) g_bsum[tid] = sh[tid] - v;      // exclusive block offsets
    if (tid == 127) g_bsum[NB] = sh[127];         // total (== E)
}

// stage 3: apply block offsets; also zero g_cnt for the scatter pass
__global__ void k_scan3(int N, int NB) {
    int i = blockIdx.x * SCAN_B + threadIdx.x;
    if (i < N) {
        g_rowptr[i] += g_bsum[blockIdx.x];
        g_cnt[i] = 0;
    }
    if (i == 0) g_rowptr[N] = g_bsum[NB];
}

__global__ void k_scatter(const int* __restrict__ src, const int* __restrict__ dst, int E) {
    int e = blockIdx.x * blockDim.x + threadIdx.x;
    if (e < E) {
        int s = src[e];
        int p = g_rowptr[s] + atomicAdd(&g_cnt[s], 1);
        g_srcc[p] = s;
        g_dstc[p] = dst[e];
    }
}

// ------ flat per-edge logits in CSR slot order (edge-parallel, high MLP) ------
__global__ void k_edge(const float* __restrict__ ps, const float* __restrict__ be, int E) {
    int e = blockIdx.x * blockDim.x + threadIdx.x;
    if (e < E) {
        float v = ps[g_srcc[e]] + ps[g_dstc[e]] + be[0];
        g_ex[e] = __expf(tanhf(v));   // |tanh|<1 -> no max-subtraction needed
    }
}

// -------------------- tensor-core helpers (R13/R16-proven) --------------------
__device__ __forceinline__ void ldm_x4(uint32_t& r0, uint32_t& r1, uint32_t& r2, uint32_t& r3,
                                       uint32_t addr) {
    asm volatile("ldmatrix.sync.aligned.m8n8.x4.shared.b16 {%0,%1,%2,%3}, [%4];\n"
                 : "=r"(r0), "=r"(r1), "=r"(r2), "=r"(r3) : "r"(addr));
}
__device__ __forceinline__ void mma_bf16(float* d,
                                         uint32_t a0, uint32_t a1, uint32_t a2, uint32_t a3,
                                         uint32_t b0, uint32_t b1) {
    asm volatile("mma.sync.aligned.m16n8k16.row.col.f32.bf16.bf16.f32 "
                 "{%0,%1,%2,%3}, {%4,%5,%6,%7}, {%8,%9}, {%0,%1,%2,%3};\n"
                 : "+f"(d[0]), "+f"(d[1]), "+f"(d[2]), "+f"(d[3])
                 : "r"(a0), "r"(a1), "r"(a2), "r"(a3), "r"(b0), "r"(b1));
}

// -------------------- fused GEMM via bf16-split HMMA (R16-proven) ----------
#define BM 128
#define BK 16

__global__ __launch_bounds__(256, 2) void k_gemm2(
    const float* __restrict__ X, int N, int K,
    const float* __restrict__ Wa, const float* __restrict__ ba,
    const float* __restrict__ We,
    const float* __restrict__ Wv, const float* __restrict__ bv,
    float* __restrict__ ps, __half2* __restrict__ vh)
{
    extern __shared__ __align__(16) char smraw[];
    __nv_bfloat16* sm = (__nv_bfloat16*)smraw;
    const int WP = K + 8;
    const int WSZ = 64 * WP;
    __nv_bfloat16* Xh = sm + 4 * WSZ;
    __nv_bfloat16* Xl = Xh + 2 * 128 * 24;

    int tid = threadIdx.x;
    int bm = blockIdx.x * BM;
    int warp = tid >> 5, lane = tid & 31;

    int kq = K >> 2;
    for (int idx = tid; idx < 16 * K; idx += 256) {
        int row = idx / kq;
        int k4 = (idx - row * kq) * 4;
        float4 qa = *(const float4*)&Wa[(size_t)row * K + k4];
        float4 qv = *(const float4*)&Wv[(size_t)row * K + k4];
        float va[4] = {qa.x, qa.y, qa.z, qa.w};
        float vv[4] = {qv.x, qv.y, qv.z, qv.w};
        __nv_bfloat16 ah[4], al[4], vh4[4], vl[4];
        #pragma unroll
        for (int u = 0; u < 4; u++) {
            ah[u] = __float2bfloat16(va[u]);
            al[u] = __float2bfloat16(va[u] - __bfloat162float(ah[u]));
            vh4[u] = __float2bfloat16(vv[u]);
            vl[u] = __float2bfloat16(vv[u] - __bfloat162float(vh4[u]));
        }
        *(uint2*)&sm[0 * WSZ + row * WP + k4] = *(uint2*)ah;
        *(uint2*)&sm[1 * WSZ + row * WP + k4] = *(uint2*)al;
        *(uint2*)&sm[2 * WSZ + row * WP + k4] = *(uint2*)vh4;
        *(uint2*)&sm[3 * WSZ + row * WP + k4] = *(uint2*)vl;
    }

    int xrow = tid >> 1;
    int xkh = (tid & 1) * 8;
    float4 pf0, pf1;

    {
        int gm = bm + xrow;
        if (gm < N) {
            pf0 = *(const float4*)&X[(size_t)gm * K + xkh];
            pf1 = *(const float4*)&X[(size_t)gm * K + xkh + 4];
        } else { pf0 = make_float4(0,0,0,0); pf1 = make_float4(0,0,0,0); }
    }
    {
        float v8[8] = {pf0.x, pf0.y, pf0.z, pf0.w, pf1.x, pf1.y, pf1.z, pf1.w};
        __nv_bfloat16 h8[8], l8[8];
        #pragma unroll
        for (int u = 0; u < 8; u++) {
            h8[u] = __float2bfloat16(v8[u]);
            l8[u] = __float2bfloat16(v8[u] - __bfloat162float(h8[u]));
        }
        *(uint4*)&Xh[xrow * 24 + xkh] = *(uint4*)h8;
        *(uint4*)&Xl[xrow * 24 + xkh] = *(uint4*)l8;
    }
    __syncthreads();

    uint32_t smbase = (uint32_t)__cvta_generic_to_shared(sm);
    int g = lane >> 3, li = lane & 7;
    int wm = warp * 16;
    uint32_t aAh = smbase + (uint32_t)(8 * WSZ)
                 + (uint32_t)(((wm + (g & 1) * 8 + li) * 24 + (g >> 1) * 8) * 2);
    const uint32_t XBUF = 128 * 24 * 2;
    const uint32_t HL = 2 * XBUF;
    uint32_t bOff = (uint32_t)((li * WP + (g & 1) * 8 + (g >> 1) * WSZ) * 2);
    const uint32_t offWv = (uint32_t)(2 * WSZ * 2);
    const uint32_t ntStep = (uint32_t)(16 * WP);

    float accA[8][4] = {};
    float accV[8][4] = {};

    int T = K / BK;
    for (int t = 0; t < T; t++) {
        if (t + 1 < T) {
            int gm = bm + xrow;
            int koff = (t + 1) * BK + xkh;
            if (gm < N) {
                pf0 = *(const float4*)&X[(size_t)gm * K + koff];
                pf1 = *(const float4*)&X[(size_t)gm * K + koff + 4];
            } else { pf0 = make_float4(0,0,0,0); pf1 = make_float4(0,0,0,0); }
        }

        uint32_t bufo = (uint32_t)((t & 1) * XBUF);
        uint32_t a0, a1, a2, a3, l0, l1, l2, l3;
        ldm_x4(a0, a1, a2, a3, aAh + bufo);
        ldm_x4(l0, l1, l2, l3, aAh + bufo + HL);
        uint32_t wk = smbase + bOff + (uint32_t)(t * 32);
        #pragma unroll
        for (int nt = 0; nt < 8; nt++) {
            uint32_t b0, b1, b2, b3;
            ldm_x4(b0, b1, b2, b3, wk + nt * ntStep);
            mma_bf16(accA[nt], a0, a1, a2, a3, b0, b1);
            mma_bf16(accA[nt], a0, a1, a2, a3, b2, b3);
            mma_bf16(accA[nt], l0, l1, l2, l3, b0, b1);
            ldm_x4(b0, b1, b2, b3, wk + offWv + nt * ntStep);
            mma_bf16(accV[nt], a0, a1, a2, a3, b0, b1);
            mma_bf16(accV[nt], a0, a1, a2, a3, b2, b3);
            mma_bf16(accV[nt], l0, l1, l2, l3, b0, b1);
        }

        if (t + 1 < T) {
            float v8[8] = {pf0.x, pf0.y, pf0.z, pf0.w, pf1.x, pf1.y, pf1.z, pf1.w};
            __nv_bfloat16 h8[8], l8[8];
            #pragma unroll
            for (int u = 0; u < 8; u++) {
                h8[u] = __float2bfloat16(v8[u]);
                l8[u] = __float2bfloat16(v8[u] - __bfloat162float(h8[u]));
            }
            int boff = ((t + 1) & 1) * 128 * 24;
            *(uint4*)&Xh[boff + xrow * 24 + xkh] = *(uint4*)h8;
            *(uint4*)&Xl[boff + xrow * 24 + xkh] = *(uint4*)l8;
            __syncthreads();
        }
    }

    int r0 = bm + wm + (lane >> 2);
    int r1 = r0 + 8;
    int cq = (lane & 3) * 2;
    float psum0 = 0.f, psum1 = 0.f;
    #pragma unroll
    for (int nt = 0; nt < 8; nt++) {
        int c0 = nt * 8 + cq;
        float we0 = We[c0], we1 = We[c0 + 1];
        float ba0 = ba[c0], ba1 = ba[c0 + 1];
        float bv0 = bv[c0], bv1 = bv[c0 + 1];
        psum0 += tanhf(accA[nt][0] + ba0) * we0 + tanhf(accA[nt][1] + ba1) * we1;
        psum1 += tanhf(accA[nt][2] + ba0) * we0 + tanhf(accA[nt][3] + ba1) * we1;
        int hcol = nt * 4 + (lane & 3);
        if (r0 < N)
            vh[(size_t)r0 * 32 + hcol] =
                __floats2half2_rn(tanhf(accV[nt][0] + bv0), tanhf(accV[nt][1] + bv1));
        if (r1 < N)
            vh[(size_t)r1 * 32 + hcol] =
                __floats2half2_rn(tanhf(accV[nt][2] + bv0), tanhf(accV[nt][3] + bv1));
    }
    psum0 += __shfl_xor_sync(0xffffffffu, psum0, 1);
    psum0 += __shfl_xor_sync(0xffffffffu, psum0, 2);
    psum1 += __shfl_xor_sync(0xffffffffu, psum1, 1);
    psum1 += __shfl_xor_sync(0xffffffffu, psum1, 2);
    if ((lane & 3) == 0) {
        if (r0 < N) ps[r0] = psum0;
        if (r1 < N) ps[r1] = psum1;
    }
}

// ---------- aggregation + row std-norm (warp per node; ex precomputed) ----------
// pass2 loop is a byte-copy of the R16 fallback path (proven on HW).
__global__ __launch_bounds__(256) void k_agg(float* __restrict__ Out, int N)
{
    int wid = (blockIdx.x * blockDim.x + threadIdx.x) >> 5;
    int lane = threadIdx.x & 31;
    if (wid >= N) return;

    int r0 = g_rowptr[wid];
    int r1 = g_rowptr[wid + 1];

    // pass 1: coalesced softmax denominator (ex precomputed by k_edge)
    float sum = 0.f;
    for (int p = r0 + lane; p < r1; p += 32) sum += g_ex[p];
    #pragma unroll
    for (int off = 16; off > 0; off >>= 1) sum += __shfl_xor_sync(0xffffffffu, sum, off);
    float inv = 1.0f / sum;

    // pass 2: 4 edges per warp-iteration, uint4 row gathers (R16-proven loop)
    int g = lane >> 3;    // 0..3  edge within group-of-4
    int c = lane & 7;     // 0..7  column chunk (8 cols)
    const uint4* v4 = (const uint4*)g_vh;    // v row = 8 uint4 (64 fp16)
    float acc[8] = {};
    for (int base = r0; base < r1; base += 4) {
        int p = base + g;
        float att = 0.f;
        int d = 0;
        if (p < r1) {
            att = g_ex[p] * inv;
            d = g_dstc[p];
        }
        uint4 q = v4[(size_t)d * 8 + c];
        const __half2* hq = (const __half2*)&q;
        #pragma unroll
        for (int t = 0; t < 4; t++) {
            float2 f = __half22float2(hq[t]);
            acc[2 * t]     = fmaf(att, f.x, acc[2 * t]);
            acc[2 * t + 1] = fmaf(att, f.y, acc[2 * t + 1]);
        }
    }
    #pragma unroll
    for (int t = 0; t < 8; t++) {
        acc[t] += __shfl_xor_sync(0xffffffffu, acc[t], 8);
        acc[t] += __shfl_xor_sync(0xffffffffu, acc[t], 16);
    }

    float s = 0.f;
    #pragma unroll
    for (int t = 0; t < 8; t++) s += acc[t];
    #pragma unroll
    for (int off = 4; off > 0; off >>= 1) s += __shfl_xor_sync(0xffffffffu, s, off);
    float mean = s * (1.0f / 64.0f);
    float q2 = 0.f;
    #pragma unroll
    for (int t = 0; t < 8; t++) { float dq = acc[t] - mean; q2 = fmaf(dq, dq, q2); }
    #pragma unroll
    for (int off = 4; off > 0; off >>= 1) q2 += __shfl_xor_sync(0xffffffffu, q2, off);
    float inv_std = rsqrtf(q2 * (1.0f / 63.0f));

    if (g < 2) {
        float4 o;
        o.x = acc[g * 4 + 0] * inv_std;
        o.y = acc[g * 4 + 1] * inv_std;
        o.z = acc[g * 4 + 2] * inv_std;
        o.w = acc[g * 4 + 3] * inv_std;
        *(float4*)&Out[(size_t)wid * 64 + c * 8 + g * 4] = o;
    }
}

// -------------------- launch --------------------
extern "C" void kernel_launch(void* const* d_in, const int* in_sizes, int n_in,
                              void* d_out, int out_size)
{
    const float* h   = (const float*)d_in[0];
    const int*   ei  = (const int*)d_in[1];
    const float* W11 = (const float*)d_in[2];
    const float* b11 = (const float*)d_in[3];
    const float* W12 = (const float*)d_in[4];
    const float* b12 = (const float*)d_in[5];
    const float* W13 = (const float*)d_in[6];
    const float* b13 = (const float*)d_in[7];
    const float* W21 = (const float*)d_in[8];
    const float* b21 = (const float*)d_in[9];
    const float* W22 = (const float*)d_in[10];
    const float* b22 = (const float*)d_in[11];
    const float* W23 = (const float*)d_in[12];
    const float* b23 = (const float*)d_in[13];

    int N = in_sizes[0] / 128;
    int E = in_sizes[1] / 2;
    const int* src = ei;
    const int* dst = ei + E;

    float*   ps_dev; cudaGetSymbolAddress((void**)&ps_dev, g_ps);
    __half2* vh_dev; cudaGetSymbolAddress((void**)&vh_dev, g_vh);
    float*   h1_dev; cudaGetSymbolAddress((void**)&h1_dev, g_h1);
    int*     cnt_dev; cudaGetSymbolAddress((void**)&cnt_dev, g_cnt);

    size_t smem1 = (size_t)(4 * 64 * (128 + 8) + 4 * 128 * 24) * 2;  // K=128
    size_t smem2 = (size_t)(4 * 64 * (64 + 8) + 4 * 128 * 24) * 2;   // K=64
    cudaFuncSetAttribute(k_gemm2, cudaFuncAttributeMaxDynamicSharedMemorySize, (int)smem1);

    int gemm_blocks = (N + BM - 1) / BM;
    int edge_blocks = (E + 255) / 256;
    int agg_blocks = (int)(((long long)N * 32 + 255) / 256);
    int NB = (N + SCAN_B - 1) / SCAN_B;   // 98 scan blocks

    // Side stream: CSR build overlapped with the layer-1 GEMM (fork/join off
    // the capture stream). Streams/events intentionally leaked (host-side only).
    cudaStream_t s2;
    cudaStreamCreateWithFlags(&s2, cudaStreamNonBlocking);
    cudaEvent_t evFork, evJoin;
    cudaEventCreateWithFlags(&evFork, cudaEventDisableTiming);
    cudaEventCreateWithFlags(&evJoin, cudaEventDisableTiming);

    cudaEventRecord(evFork, 0);
    cudaStreamWaitEvent(s2, evFork, 0);

    // ---- CSR build on s2 (parallel scan; scatter records src + dst) ----
    cudaMemsetAsync(cnt_dev, 0, (size_t)N * sizeof(int), s2);
    k_count<<<edge_blocks, 256, 0, s2>>>(src, E);
    k_scan1<<<NB, SCAN_B, 0, s2>>>(N);
    k_scan2<<<1, 128, 0, s2>>>(NB);
    k_scan3<<<NB, SCAN_B, 0, s2>>>(N, NB);
    k_scatter<<<edge_blocks, 256, 0, s2>>>(src, dst, E);

    // ---- layer-1 GEMM on main stream (independent of CSR) ----
    k_gemm2<<<gemm_blocks, 256, smem1>>>(h, N, 128, W11, b11, W12, W13, b13, ps_dev, vh_dev);

    cudaEventRecord(evJoin, s2);
    cudaStreamWaitEvent(0, evJoin, 0);

    // ---- layer 1: edge logits + aggregation ----
    k_edge<<<edge_blocks, 256>>>(ps_dev, b12, E);
    k_agg<<<agg_blocks, 256>>>(h1_dev, N);

    // ---- layer 2 ----
    k_gemm2<<<gemm_blocks, 256, smem2>>>(h1_dev, N, 64, W21, b21, W22, W23, b23, ps_dev, vh_dev);
    k_edge<<<edge_blocks, 256>>>(ps_dev, b22, E);
    k_agg<<<agg_blocks, 256>>>((float*)d_out, N);
}